// round 13
// baseline (speedup 1.0000x reference)
#include <cuda_runtime.h>
#include <math.h>

#define T_LEN 4096
#define H_DIM 1024
#define NCOL  6144   // 2 dirs * 3 gates * H

// Scratch (allocation-free rule: __device__ globals)
static __device__ float g_xproj[(size_t)T_LEN * NCOL];   // ~100.7 MB
static __device__ float g_h[2][2][H_DIM];                // [buf parity][dir][j]
static __device__ int   g_flags[128][32];                // 1 flag per 128B line

// ---- packed f32x2 helpers -------------------------------------------------
__device__ __forceinline__ void ffma2(unsigned long long &d,
                                      unsigned long long a,
                                      unsigned long long b) {
    asm("fma.rn.f32x2 %0, %1, %2, %0;" : "+l"(d) : "l"(a), "l"(b));
}
__device__ __forceinline__ unsigned long long pack2(float lo, float hi) {
    unsigned long long r;
    asm("mov.b64 %0, {%1, %2};" : "=l"(r) : "f"(lo), "f"(hi));
    return r;
}
__device__ __forceinline__ void unpack2(unsigned long long v, float &lo, float &hi) {
    asm("mov.b64 {%0, %1}, %2;" : "=f"(lo), "=f"(hi) : "l"(v));
}
// ---- release/acquire flag ops --------------------------------------------
__device__ __forceinline__ void st_release_gpu(int* p, int v) {
    asm volatile("st.release.gpu.global.b32 [%0], %1;" :: "l"(p), "r"(v) : "memory");
}
__device__ __forceinline__ int ld_acquire_gpu(const int* p) {
    int v;
    asm volatile("ld.acquire.gpu.global.b32 %0, [%1];" : "=r"(v) : "l"(p) : "memory");
    return v;
}

// ---------------------------------------------------------------------------
// Kernel 1: x_proj = emb[x] @ w_ih^T + b_ih. 128x128x16 SGEMM, FFMA2 inner.
// (unchanged from the round-9 PASS)
// ---------------------------------------------------------------------------
__global__ void __launch_bounds__(256) gemm_xproj_kernel(
    const int*   __restrict__ x,
    const float* __restrict__ emb,
    const float* __restrict__ w,      // (6144, 1024) row-major
    const float* __restrict__ bias)   // (6144)
{
    __shared__ float As[16][132];
    __shared__ float Bs[16][132];

    const int tid = threadIdx.x;
    const int m0 = blockIdx.y * 128;
    const int n0 = blockIdx.x * 128;

    const int r0 = tid >> 2;      // 0..63
    const int c4 = tid & 3;       // 0..3

    const float* arow0 = emb + (size_t)__ldg(x + m0 + r0)      * H_DIM + c4 * 4;
    const float* arow1 = emb + (size_t)__ldg(x + m0 + r0 + 64) * H_DIM + c4 * 4;
    const float* brow0 = w + (size_t)(n0 + r0)      * H_DIM + c4 * 4;
    const float* brow1 = w + (size_t)(n0 + r0 + 64) * H_DIM + c4 * 4;

    const int tx = tid & 15;
    const int ty = tid >> 4;

    unsigned long long acc2[8][4];
    #pragma unroll
    for (int i = 0; i < 8; ++i)
        #pragma unroll
        for (int jj = 0; jj < 4; ++jj) acc2[i][jj] = 0ull;

    for (int k0 = 0; k0 < H_DIM; k0 += 16) {
        float4 a0 = *(const float4*)(arow0 + k0);
        float4 a1 = *(const float4*)(arow1 + k0);
        float4 b0 = *(const float4*)(brow0 + k0);
        float4 b1 = *(const float4*)(brow1 + k0);
        __syncthreads();
        As[c4*4+0][r0]    = a0.x; As[c4*4+1][r0]    = a0.y;
        As[c4*4+2][r0]    = a0.z; As[c4*4+3][r0]    = a0.w;
        As[c4*4+0][r0+64] = a1.x; As[c4*4+1][r0+64] = a1.y;
        As[c4*4+2][r0+64] = a1.z; As[c4*4+3][r0+64] = a1.w;
        Bs[c4*4+0][r0]    = b0.x; Bs[c4*4+1][r0]    = b0.y;
        Bs[c4*4+2][r0]    = b0.z; Bs[c4*4+3][r0]    = b0.w;
        Bs[c4*4+0][r0+64] = b1.x; Bs[c4*4+1][r0+64] = b1.y;
        Bs[c4*4+2][r0+64] = b1.z; Bs[c4*4+3][r0+64] = b1.w;
        __syncthreads();
        #pragma unroll
        for (int k = 0; k < 16; ++k) {
            float a[8];
            *(float4*)(a + 0) = *(const float4*)&As[k][ty * 8];
            *(float4*)(a + 4) = *(const float4*)&As[k][ty * 8 + 4];
            ulonglong2 bq0 = *(const ulonglong2*)&Bs[k][tx * 8];
            ulonglong2 bq1 = *(const ulonglong2*)&Bs[k][tx * 8 + 4];
            #pragma unroll
            for (int i = 0; i < 8; ++i) {
                unsigned long long pa = pack2(a[i], a[i]);
                ffma2(acc2[i][0], pa, bq0.x);
                ffma2(acc2[i][1], pa, bq0.y);
                ffma2(acc2[i][2], pa, bq1.x);
                ffma2(acc2[i][3], pa, bq1.y);
            }
        }
    }

    float bb[8];
    *(float4*)(bb + 0) = *(const float4*)(bias + n0 + tx * 8);
    *(float4*)(bb + 4) = *(const float4*)(bias + n0 + tx * 8 + 4);
    #pragma unroll
    for (int i = 0; i < 8; ++i) {
        float c[8];
        #pragma unroll
        for (int jj = 0; jj < 4; ++jj) unpack2(acc2[i][jj], c[2*jj], c[2*jj+1]);
        float* crow = g_xproj + (size_t)(m0 + ty * 8 + i) * NCOL + n0 + tx * 8;
        float4 v0 = make_float4(c[0] + bb[0], c[1] + bb[1], c[2] + bb[2], c[3] + bb[3]);
        float4 v1 = make_float4(c[4] + bb[4], c[5] + bb[5], c[6] + bb[6], c[7] + bb[7]);
        *(float4*)(crow)     = v0;
        *(float4*)(crow + 4) = v1;
    }
}

// ---------------------------------------------------------------------------
// Kernel 2: persistent GRU scan. Same partition + FFMA2 math as round-9 PASS.
// Sync path reworked: padded per-line flags, release-store publish,
// fused per-producer acquire-poll + h-segment load (one barrier removed).
// ---------------------------------------------------------------------------
__global__ void __launch_bounds__(512, 1) gru_scan_kernel(
    const float* __restrict__ w_hh,   // (6144, 1024)
    const float* __restrict__ b_hh,   // (6144)
    float* __restrict__ out)          // (T, 2048) then hidden row
{
    __shared__ float hsm[H_DIM];
    __shared__ float hnew_sm[16];

    const int tid   = threadIdx.x;
    const int lane  = tid & 31;
    const int wrp   = tid >> 5;            // 0..15
    const int blk   = blockIdx.x;          // 0..127
    const int d     = blk >> 6;            // 0 or 1
    const int jbase = (blk & 63) * 16;
    const int j     = jbase + wrp;         // unit 0..1023

    const size_t rr = (size_t)(d * 3072 + j) * H_DIM;
    const size_t rz = rr + (size_t)1024 * H_DIM;
    const size_t rn = rz + (size_t)1024 * H_DIM;

    // Weight preload as packed pairs: lane covers h = i*128 + lane*4 + {0..3}
    unsigned long long wr2[16], wz2[16], wn2[16];
    {
        const ulonglong2* pr = (const ulonglong2*)(w_hh + rr);
        const ulonglong2* pz = (const ulonglong2*)(w_hh + rz);
        const ulonglong2* pn = (const ulonglong2*)(w_hh + rn);
        #pragma unroll
        for (int i = 0; i < 8; ++i) {
            ulonglong2 a = pr[i * 32 + lane]; wr2[2*i] = a.x; wr2[2*i+1] = a.y;
            ulonglong2 b = pz[i * 32 + lane]; wz2[2*i] = b.x; wz2[2*i+1] = b.y;
            ulonglong2 c = pn[i * 32 + lane]; wn2[2*i] = c.x; wn2[2*i+1] = c.y;
        }
    }
    float bhr = 0.f, bhz = 0.f, bhn = 0.f;
    if (lane == 0) {
        bhr = __ldg(b_hh + d * 3072 + j);
        bhz = __ldg(b_hh + d * 3072 + 1024 + j);
        bhn = __ldg(b_hh + d * 3072 + 2048 + j);
    }

    const float* xp = g_xproj + d * 3072 + j;

    for (int s = 0; s < T_LEN; ++s) {
        // Prefetch x-gate inputs (independent of h; hides DRAM latency)
        float xr = 0.f, xz = 0.f, xn = 0.f;
        if (lane == 0) {
            const float* p = xp + (size_t)s * NCOL;
            xr = __ldg(p);
            xz = __ldg(p + 1024);
            xn = __ldg(p + 2048);
        }

        // Fused poll+stage: thread t (t<64) waits on producer t of this
        // direction, then immediately loads that producer's 16 h floats.
        // Padded flags: one 128B line per producer -> no LTS queueing.
        if (tid < 64) {
            const int* fp = &g_flags[(d << 6) + tid][0];
            while (ld_acquire_gpu(fp) < s) { }
            const float4* hb = (const float4*)(&g_h[s & 1][d][tid * 16]);
            float4 v0 = __ldcg(hb + 0);
            float4 v1 = __ldcg(hb + 1);
            float4 v2 = __ldcg(hb + 2);
            float4 v3 = __ldcg(hb + 3);
            float4* dst = (float4*)&hsm[tid * 16];
            dst[0] = v0; dst[1] = v1; dst[2] = v2; dst[3] = v3;
        }
        __syncthreads();

        // 3 dot products of length 1024 via packed FFMA2 (48 per thread)
        unsigned long long ar2 = 0ull, az2 = 0ull, an2 = 0ull;
        #pragma unroll
        for (int i = 0; i < 8; ++i) {
            ulonglong2 hv = ((const ulonglong2*)hsm)[i * 32 + lane];
            ffma2(ar2, wr2[2*i],   hv.x);
            ffma2(ar2, wr2[2*i+1], hv.y);
            ffma2(az2, wz2[2*i],   hv.x);
            ffma2(az2, wz2[2*i+1], hv.y);
            ffma2(an2, wn2[2*i],   hv.x);
            ffma2(an2, wn2[2*i+1], hv.y);
        }
        float lo, hi, ar, az, an;
        unpack2(ar2, lo, hi); ar = lo + hi;
        unpack2(az2, lo, hi); az = lo + hi;
        unpack2(an2, lo, hi); an = lo + hi;
        #pragma unroll
        for (int o = 16; o > 0; o >>= 1) {
            ar += __shfl_xor_sync(0xffffffffu, ar, o);
            az += __shfl_xor_sync(0xffffffffu, az, o);
            an += __shfl_xor_sync(0xffffffffu, an, o);
        }

        if (lane == 0) {
            float r = 1.f / (1.f + __expf(-(xr + ar + bhr)));
            float z = 1.f / (1.f + __expf(-(xz + az + bhz)));
            float n = tanhf(xn + r * (an + bhn));
            float hprev = hsm[j];
            hnew_sm[wrp] = (1.f - z) * n + z * hprev;
        }
        __syncthreads();

        // Publish: outputs row slice; h slice + release-flag (orders the
        // preceding h stores without a full membar).
        if (tid < 16)
            out[(size_t)s * 2048 + d * 1024 + jbase + tid] = hnew_sm[tid];
        if (tid == 0) {
            float4*       dst = (float4*)(&g_h[(s + 1) & 1][d][jbase]);
            const float4* src = (const float4*)hnew_sm;
            dst[0] = src[0]; dst[1] = src[1]; dst[2] = src[2]; dst[3] = src[3];
            st_release_gpu(&g_flags[blk][0], s + 1);
        }
    }
}

// ---------------------------------------------------------------------------
// Kernel 3: hidden = h_T[dir0] + h_T[dir1]  (final state lives in buffer 0)
// ---------------------------------------------------------------------------
__global__ void hidden_kernel(float* __restrict__ out)
{
    int j = threadIdx.x;
    out[(size_t)T_LEN * 2048 + j] = g_h[0][0][j] + g_h[0][1][j];
}

// ---------------------------------------------------------------------------
extern "C" void kernel_launch(void* const* d_in, const int* in_sizes, int n_in,
                              void* d_out, int out_size)
{
    const int*   x    = (const int*)d_in[0];
    const float* emb  = (const float*)d_in[1];
    const float* w_ih = (const float*)d_in[2];
    const float* w_hh = (const float*)d_in[3];
    const float* b_ih = (const float*)d_in[4];
    const float* b_hh = (const float*)d_in[5];
    float* out = (float*)d_out;

    void* pflags = nullptr;
    void* ph     = nullptr;
    cudaGetSymbolAddress(&pflags, g_flags);
    cudaGetSymbolAddress(&ph,     g_h);
    cudaMemsetAsync(pflags, 0, sizeof(int) * 128 * 32, 0);
    cudaMemsetAsync(ph,     0, sizeof(float) * 2 * 2 * H_DIM, 0);

    gemm_xproj_kernel<<<dim3(NCOL / 128, T_LEN / 128), 256>>>(x, emb, w_ih, b_ih);
    gru_scan_kernel<<<128, 512>>>(w_hh, b_hh, out);
    hidden_kernel<<<1, H_DIM>>>(out);
}